// round 3
// baseline (speedup 1.0000x reference)
#include <cuda_runtime.h>
#include <cuda_bf16.h>
#include <cstdint>

#define Bn   128
#define Sn   512
#define Ln   64
#define NPAIRS ((Bn-1)*Sn)       // 65024
#define PPB  128
#define NBLK (NPAIRS/PPB)        // 508
#define NQ   (Bn*Sn)             // 65536

#define LOG2E 1.4426950408889634f
#define LN2f  0.6931471805599453f

__device__ double g_alpha[Ln];
__device__ double g_score;

__device__ __forceinline__ float ex2f(float x){ float y; asm("ex2.approx.f32 %0, %1;" : "=f"(y) : "f"(x)); return y; }
__device__ __forceinline__ float lg2f_(float x){ float y; asm("lg2.approx.f32 %0, %1;" : "=f"(y) : "f"(x)); return y; }
__device__ __forceinline__ void ffma2(unsigned long long& d, unsigned long long a, unsigned long long b){
    asm("fma.rn.f32x2 %0, %1, %2, %0;" : "+l"(d) : "l"(a), "l"(b));
}

// ---------------------------------------------------------------------------
// Kernel 0: zero global accumulators.
// ---------------------------------------------------------------------------
__global__ void initz_kernel(){
    int t = threadIdx.x;
    if (t < Ln)  g_alpha[t] = 0.0;
    if (t == Ln) g_score = 0.0;
}

// ---------------------------------------------------------------------------
// Kernel 1: fused alpha.  Per block: 128 (b,s) pairs.
//   - build expT pair-duplicated in smem (from trans, L2-resident)
//   - load raw emit tile, ex2, store transposed in smem
//   - inner loop: packed fma.rn.f32x2, 4 i x 8 p per thread
//   - lg2, mask, block-reduce, atomicAdd per-i partials
// ---------------------------------------------------------------------------
__global__ __launch_bounds__(256) void alpha_kernel(
    const float* __restrict__ emit, const float* __restrict__ trans,
    const int* __restrict__ mask)
{
    __shared__ float sT2[Ln*128];      // [j*128 + 2i + {0,1}]  (value duplicated)
    __shared__ float est[Ln*132];      // [j*132 + p]
    __shared__ float flags[PPB];

    int t  = threadIdx.x;
    int p0 = blockIdx.x * PPB;

    // expT (duplicated pairs). o = j*64 + i over 4096.
    #pragma unroll
    for (int it = 0; it < 16; ++it){
        int o = t + it*256;
        int i = o & 63, j = o >> 6;
        float v = ex2f(trans[i*64 + j] * LOG2E);
        sT2[j*128 + 2*i]     = v;
        sT2[j*128 + 2*i + 1] = v;
    }
    // emit tile -> ex2 -> transposed est.  thread: p = t&127, j-range 32*(t>>7).
    {
        int p  = t & 127;
        int jh = (t >> 7) * 32;
        const float* src = emit + ((size_t)(p0 + Sn + p))*Ln + jh;
        #pragma unroll
        for (int k = 0; k < 8; ++k){
            float4 v = *(const float4*)(src + 4*k);
            int j = jh + 4*k;
            est[(j  )*132 + p] = ex2f(v.x * LOG2E);
            est[(j+1)*132 + p] = ex2f(v.y * LOG2E);
            est[(j+2)*132 + p] = ex2f(v.z * LOG2E);
            est[(j+3)*132 + p] = ex2f(v.w * LOG2E);
        }
    }
    if (t < PPB){
        int p = p0 + t;
        int b = 1 + (p >> 9), s = p & 511;
        flags[t] = mask[b*Sn + s] ? 1.0f : 0.0f;
    }
    __syncthreads();

    const int i4 = t & 15;             // i = 4*i4 .. 4*i4+3
    const int pg = t >> 4;             // p = pg*8 .. pg*8+7
    unsigned long long acc[4][4];      // [k][m] = (acc(i,2m), acc(i,2m+1)) packed f32x2
    #pragma unroll
    for (int k = 0; k < 4; ++k)
        #pragma unroll
        for (int m = 0; m < 4; ++m) acc[k][m] = 0ull;

    const ulonglong2* sT2v = (const ulonglong2*)sT2;   // 4 floats each
    const ulonglong2* estv = (const ulonglong2*)est;

    #pragma unroll 4
    for (int j = 0; j < 64; ++j){
        ulonglong2 ta = sT2v[j*32 + i4*2];       // (T0,T0),(T1,T1)
        ulonglong2 tb = sT2v[j*32 + i4*2 + 1];   // (T2,T2),(T3,T3)
        ulonglong2 ea = estv[j*33 + pg*2];       // (e0,e1),(e2,e3)
        ulonglong2 eb = estv[j*33 + pg*2 + 1];   // (e4,e5),(e6,e7)
        unsigned long long tp[4] = {ta.x, ta.y, tb.x, tb.y};
        unsigned long long ep[4] = {ea.x, ea.y, eb.x, eb.y};
        #pragma unroll
        for (int k = 0; k < 4; ++k){
            ffma2(acc[k][0], tp[k], ep[0]);
            ffma2(acc[k][1], tp[k], ep[1]);
            ffma2(acc[k][2], tp[k], ep[2]);
            ffma2(acc[k][3], tp[k], ep[3]);
        }
    }

    // log2 + masked accumulate (log2 units; scale by ln2 at the end)
    float csum[4] = {0.f, 0.f, 0.f, 0.f};
    #pragma unroll
    for (int m = 0; m < 4; ++m){
        float f0 = flags[(pg << 3) + 2*m];
        float f1 = flags[(pg << 3) + 2*m + 1];
        #pragma unroll
        for (int k = 0; k < 4; ++k){
            float lo = __uint_as_float((unsigned)(acc[k][m] & 0xffffffffull));
            float hi = __uint_as_float((unsigned)(acc[k][m] >> 32));
            csum[k] += f0 * lg2f_(lo) + f1 * lg2f_(hi);
        }
    }

    __syncthreads();                   // est no longer needed
    float* red = est;                  // red[pg*64 + i]
    #pragma unroll
    for (int k = 0; k < 4; ++k) red[pg*64 + (i4 << 2) + k] = csum[k];
    __syncthreads();

    if (t < Ln){
        float s = 0.f;
        #pragma unroll
        for (int g = 0; g < 16; ++g) s += red[g*64 + t];
        atomicAdd(&g_alpha[t], (double)(s * LN2f));
    }
}

// ---------------------------------------------------------------------------
// Kernel 2: per-step label score, one (b,s) per thread (max MLP).
// ---------------------------------------------------------------------------
__global__ __launch_bounds__(256) void score_main_kernel(
    const float* __restrict__ emit, const int* __restrict__ labels,
    const int* __restrict__ mask, const float* __restrict__ trans)
{
    int t = threadIdx.x;
    int g = blockIdx.x*256 + t;        // 0..65535
    float v = 0.f;
    if (mask[g]){
        int l = labels[g];
        v = emit[(size_t)g*Ln + l];
        if (g & 511) v += trans[labels[g-1]*Ln + l];
    }
    #pragma unroll
    for (int o = 16; o; o >>= 1) v += __shfl_down_sync(0xffffffffu, v, o);
    __shared__ float sp[8];
    if ((t & 31) == 0) sp[t >> 5] = v;
    __syncthreads();
    if (t == 0){
        double tot = 0.0;
        #pragma unroll
        for (int i = 0; i < 8; ++i) tot += (double)sp[i];
        atomicAdd(&g_score, tot);
    }
}

// ---------------------------------------------------------------------------
// Kernel 3: start/end transition score, one warp per batch.
// ---------------------------------------------------------------------------
__global__ __launch_bounds__(256) void score_ends_kernel(
    const int* __restrict__ labels, const int* __restrict__ mask,
    const float* __restrict__ strans, const float* __restrict__ etrans)
{
    int t = threadIdx.x;
    int lane = t & 31;
    int b = (blockIdx.x << 3) + (t >> 5);   // 16 blocks x 8 warps = 128
    const int* mk  = mask + b*Sn;
    const int* lab = labels + b*Sn;
    int cnt = 0;
    #pragma unroll
    for (int k = 0; k < 16; ++k) cnt += mk[lane + 32*k] ? 1 : 0;
    #pragma unroll
    for (int o = 16; o; o >>= 1) cnt += __shfl_down_sync(0xffffffffu, cnt, o);
    if (lane == 0){
        int end = cnt - 1; if (end < 0) end = 0;
        atomicAdd(&g_score, (double)strans[lab[0]] + (double)etrans[lab[end]]);
    }
}

// ---------------------------------------------------------------------------
// Kernel 4: finalize.
// ---------------------------------------------------------------------------
__global__ void fin_kernel(const float* __restrict__ emit, float* __restrict__ out){
    __shared__ double sa[Ln];
    int t = threadIdx.x;
    if (t < Ln) sa[t] = g_alpha[t] + (double)emit[t];
    __syncthreads();
    if (t == 0){
        double m = sa[0];
        for (int i = 1; i < Ln; ++i) if (sa[i] > m) m = sa[i];
        double s = 0.0;
        for (int i = 0; i < Ln; ++i) s += exp(sa[i] - m);
        double logZ = m + log(s);
        out[0] = (float)((logZ - g_score) / (double)Bn);
    }
}

// ---------------------------------------------------------------------------
extern "C" void kernel_launch(void* const* d_in, const int* in_sizes, int n_in,
                              void* d_out, int out_size)
{
    const float* emit   = (const float*)d_in[0];
    const int*   labels = (const int*)d_in[1];
    const int*   mask   = (const int*)d_in[2];
    const float* trans  = (const float*)d_in[3];
    const float* strans = (const float*)d_in[4];
    const float* etrans = (const float*)d_in[5];
    float* out = (float*)d_out;

    initz_kernel<<<1, 128>>>();
    alpha_kernel<<<NBLK, 256>>>(emit, trans, mask);
    score_main_kernel<<<NQ/256, 256>>>(emit, labels, mask, trans);
    score_ends_kernel<<<16, 256>>>(labels, mask, strans, etrans);
    fin_kernel<<<1, 64>>>(emit, out);
}

// round 4
// speedup vs baseline: 1.2679x; 1.2679x over previous
#include <cuda_runtime.h>
#include <cuda_bf16.h>
#include <cstdint>

#define Bn   128
#define Sn   512
#define Ln   64
#define NPAIRS ((Bn-1)*Sn)       // 65024
#define PPB  128
#define NBLK (NPAIRS/PPB)        // 508
#define NQ   (Bn*Sn)             // 65536

#define LOG2E 1.4426950408889634f
#define LN2f  0.6931471805599453f

__device__ float  g_alpha[Ln];
__device__ double g_score;
__device__ float  gExpT[Ln*Ln];   // [j*64+i] = 2^(T[i][j]*log2e)

__device__ __forceinline__ float ex2f(float x){ float y; asm("ex2.approx.f32 %0, %1;" : "=f"(y) : "f"(x)); return y; }
__device__ __forceinline__ float lg2f_(float x){ float y; asm("lg2.approx.f32 %0, %1;" : "=f"(y) : "f"(x)); return y; }

// ---------------------------------------------------------------------------
// Kernel A: zero accumulators + build expT (transposed) once.
// ---------------------------------------------------------------------------
__global__ void initz_kernel(const float* __restrict__ trans){
    int t = threadIdx.x;
    if (t < Ln)  g_alpha[t] = 0.0f;
    if (t == Ln) g_score = 0.0;
    #pragma unroll
    for (int it = 0; it < 16; ++it){
        int o = t + it*256;          // o = j*64 + i
        int i = o & 63, j = o >> 6;
        gExpT[o] = ex2f(trans[i*64 + j] * LOG2E);
    }
}

// ---------------------------------------------------------------------------
// Kernel B: per-step label score, one (b,s) per thread.
// ---------------------------------------------------------------------------
__global__ __launch_bounds__(256) void score_main_kernel(
    const float* __restrict__ emit, const int* __restrict__ labels,
    const int* __restrict__ mask, const float* __restrict__ trans)
{
    int t = threadIdx.x;
    int g = blockIdx.x*256 + t;        // 0..65535
    float v = 0.f;
    if (mask[g]){
        int l = labels[g];
        v = emit[(size_t)g*Ln + l];
        if (g & 511) v += trans[labels[g-1]*Ln + l];
    }
    #pragma unroll
    for (int o = 16; o; o >>= 1) v += __shfl_down_sync(0xffffffffu, v, o);
    __shared__ float sp[8];
    if ((t & 31) == 0) sp[t >> 5] = v;
    __syncthreads();
    if (t == 0){
        double tot = 0.0;
        #pragma unroll
        for (int i = 0; i < 8; ++i) tot += (double)sp[i];
        atomicAdd(&g_score, tot);
    }
}

// ---------------------------------------------------------------------------
// Kernel C: start/end transition score.  One block per batch, int4 counting.
// ---------------------------------------------------------------------------
__global__ __launch_bounds__(128) void score_ends_kernel(
    const int* __restrict__ labels, const int* __restrict__ mask,
    const float* __restrict__ strans, const float* __restrict__ etrans)
{
    int b = blockIdx.x, t = threadIdx.x;
    const int4 m = ((const int4*)(mask + b*Sn))[t];     // 128 threads x 4 ints = 512
    int cnt = (m.x!=0) + (m.y!=0) + (m.z!=0) + (m.w!=0);
    #pragma unroll
    for (int o = 16; o; o >>= 1) cnt += __shfl_down_sync(0xffffffffu, cnt, o);
    __shared__ int sc[4];
    if ((t & 31) == 0) sc[t >> 5] = cnt;
    __syncthreads();
    if (t == 0){
        int c = sc[0] + sc[1] + sc[2] + sc[3];
        int end = c - 1; if (end < 0) end = 0;
        const int* lab = labels + b*Sn;
        atomicAdd(&g_score, (double)strans[lab[0]] + (double)etrans[lab[end]]);
    }
}

// ---------------------------------------------------------------------------
// Kernel D: fused alpha.  Per block: 128 (b,s) pairs.
//   est row-major [p][j] == emit layout -> pure linear float4 copy + ex2.
//   Inner loop: scalar FFMA (proven), 4 i x 8 p per thread.
// ---------------------------------------------------------------------------
__global__ __launch_bounds__(256) void alpha_kernel(
    const float* __restrict__ emit, const int* __restrict__ mask)
{
    __shared__ float sT[Ln*Ln];        // [j*64 + i]
    __shared__ float est[PPB*Ln];      // [p*64 + j]  (row-major, = emit layout)
    __shared__ float flags[PPB];

    int t  = threadIdx.x;
    int p0 = blockIdx.x * PPB;

    // expT tile (coalesced, conflict-free)
    {
        const float4* gT4 = (const float4*)gExpT;
        float4* sT4 = (float4*)sT;
        #pragma unroll
        for (int it = 0; it < 4; ++it) sT4[t + it*256] = gT4[t + it*256];
    }
    // emit tile: coalesced linear copy with ex2 applied (no transpose needed)
    {
        const float4* e4 = (const float4*)(emit + (size_t)(p0 + Sn)*Ln);
        float4* s4 = (float4*)est;
        #pragma unroll
        for (int it = 0; it < 8; ++it){
            int v = t + it*256;        // 2048 float4s
            float4 x = e4[v];
            x.x = ex2f(x.x * LOG2E);
            x.y = ex2f(x.y * LOG2E);
            x.z = ex2f(x.z * LOG2E);
            x.w = ex2f(x.w * LOG2E);
            s4[v] = x;
        }
    }
    if (t < PPB){
        int p = p0 + t;
        int b = 1 + (p >> 9), s = p & 511;
        flags[t] = mask[b*Sn + s] ? 1.0f : 0.0f;
    }
    __syncthreads();

    const int i4 = t & 15;             // i = 4*i4 .. 4*i4+3
    const int pg = t >> 4;             // p = pg*8 .. pg*8+7
    float acc[4][8];
    #pragma unroll
    for (int k = 0; k < 4; ++k)
        #pragma unroll
        for (int pp = 0; pp < 8; ++pp) acc[k][pp] = 0.0f;

    const float4* sT4 = (const float4*)sT;     // [j*16 + i4]
    const float4* eS4 = (const float4*)est;    // [p*16 + jq]

    #pragma unroll 4
    for (int jq = 0; jq < 16; ++jq){
        float4 e[8];
        #pragma unroll
        for (int pp = 0; pp < 8; ++pp) e[pp] = eS4[(pg*8 + pp)*16 + jq];
        #pragma unroll
        for (int jj = 0; jj < 4; ++jj){
            float4 tv = sT4[(jq*4 + jj)*16 + i4];
            #pragma unroll
            for (int pp = 0; pp < 8; ++pp){
                float ev = (jj == 0) ? e[pp].x : (jj == 1) ? e[pp].y :
                           (jj == 2) ? e[pp].z : e[pp].w;
                acc[0][pp] = fmaf(tv.x, ev, acc[0][pp]);
                acc[1][pp] = fmaf(tv.y, ev, acc[1][pp]);
                acc[2][pp] = fmaf(tv.z, ev, acc[2][pp]);
                acc[3][pp] = fmaf(tv.w, ev, acc[3][pp]);
            }
        }
    }

    // log2 + masked accumulate (log2 units)
    float csum[4] = {0.f, 0.f, 0.f, 0.f};
    #pragma unroll
    for (int pp = 0; pp < 8; ++pp){
        float f = flags[(pg << 3) + pp];
        #pragma unroll
        for (int k = 0; k < 4; ++k) csum[k] += f * lg2f_(acc[k][pp]);
    }

    __syncthreads();                   // est no longer needed; reuse as reduction buffer
    float* red = est;                  // red[pg*64 + i]
    #pragma unroll
    for (int k = 0; k < 4; ++k) red[pg*64 + (i4 << 2) + k] = csum[k];
    __syncthreads();

    if (t < Ln){
        float s = 0.f;
        #pragma unroll
        for (int g = 0; g < 16; ++g) s += red[g*64 + t];
        atomicAdd(&g_alpha[t], s * LN2f);
    }
}

// ---------------------------------------------------------------------------
// Kernel E: finalize.
// ---------------------------------------------------------------------------
__global__ void fin_kernel(const float* __restrict__ emit, float* __restrict__ out){
    __shared__ double sa[Ln];
    int t = threadIdx.x;
    if (t < Ln) sa[t] = (double)g_alpha[t] + (double)emit[t];   // + emit[0,0,:]
    __syncthreads();
    if (t == 0){
        double m = sa[0];
        for (int i = 1; i < Ln; ++i) if (sa[i] > m) m = sa[i];
        double s = 0.0;
        for (int i = 0; i < Ln; ++i) s += exp(sa[i] - m);
        double logZ = m + log(s);
        out[0] = (float)((logZ - g_score) / (double)Bn);
    }
}

// ---------------------------------------------------------------------------
extern "C" void kernel_launch(void* const* d_in, const int* in_sizes, int n_in,
                              void* d_out, int out_size)
{
    const float* emit   = (const float*)d_in[0];
    const int*   labels = (const int*)d_in[1];
    const int*   mask   = (const int*)d_in[2];
    const float* trans  = (const float*)d_in[3];
    const float* strans = (const float*)d_in[4];
    const float* etrans = (const float*)d_in[5];
    float* out = (float*)d_out;

    // Order chosen so alpha_kernel sits at launch index 3 (the slot ncu samples).
    initz_kernel<<<1, 256>>>(trans);
    score_main_kernel<<<NQ/256, 256>>>(emit, labels, mask, trans);
    score_ends_kernel<<<Bn, 128>>>(labels, mask, strans, etrans);
    alpha_kernel<<<NBLK, 256>>>(emit, mask);
    fin_kernel<<<1, 64>>>(emit, out);
}

// round 5
// speedup vs baseline: 4.4975x; 3.5473x over previous
#include <cuda_runtime.h>
#include <cuda_bf16.h>
#include <cstdint>

#define Bn   128
#define Sn   512
#define Ln   64
#define NPAIRS ((Bn-1)*Sn)       // 65024
#define PPB  128
#define NBLK (NPAIRS/PPB)        // 508
#define NQ   (Bn*Sn)             // 65536
#define EPITCH 132               // est column pitch (floats), 16B-aligned, conflict-safe

#define LOG2E 1.4426950408889634f
#define LN2f  0.6931471805599453f

__device__ float  g_alpha[Ln];
__device__ double g_score;
__device__ float  gExpT[Ln*Ln];   // [j*64+i] = 2^(T[i][j]*log2e)

__device__ __forceinline__ float ex2f(float x){ float y; asm("ex2.approx.f32 %0, %1;" : "=f"(y) : "f"(x)); return y; }
__device__ __forceinline__ float lg2f_(float x){ float y; asm("lg2.approx.f32 %0, %1;" : "=f"(y) : "f"(x)); return y; }

// ---------------------------------------------------------------------------
// K0: zero accumulators + build expT (transposed).  16 blocks.
// ---------------------------------------------------------------------------
__global__ void initz_kernel(const float* __restrict__ trans){
    int t = threadIdx.x;
    if (blockIdx.x == 0){
        if (t < Ln)  g_alpha[t] = 0.0f;
        if (t == Ln) g_score = 0.0;
    }
    int o = blockIdx.x*256 + t;      // o = j*64 + i
    int i = o & 63, j = o >> 6;
    gExpT[o] = ex2f(trans[i*64 + j] * LOG2E);
}

// ---------------------------------------------------------------------------
// K1: start/end transition score.  One block per batch, int4 counting.
// ---------------------------------------------------------------------------
__global__ __launch_bounds__(128) void score_ends_kernel(
    const int* __restrict__ labels, const int* __restrict__ mask,
    const float* __restrict__ strans, const float* __restrict__ etrans)
{
    int b = blockIdx.x, t = threadIdx.x;
    const int4 m = ((const int4*)(mask + b*Sn))[t];
    int cnt = (m.x!=0) + (m.y!=0) + (m.z!=0) + (m.w!=0);
    #pragma unroll
    for (int o = 16; o; o >>= 1) cnt += __shfl_down_sync(0xffffffffu, cnt, o);
    __shared__ int sc[4];
    if ((t & 31) == 0) sc[t >> 5] = cnt;
    __syncthreads();
    if (t == 0){
        int c = sc[0] + sc[1] + sc[2] + sc[3];
        int end = c - 1; if (end < 0) end = 0;
        const int* lab = labels + b*Sn;
        atomicAdd(&g_score, (double)strans[lab[0]] + (double)etrans[lab[end]]);
    }
}

// ---------------------------------------------------------------------------
// K2: per-step label score, one (b,s) per thread.
// ---------------------------------------------------------------------------
__global__ __launch_bounds__(256) void score_main_kernel(
    const float* __restrict__ emit, const int* __restrict__ labels,
    const int* __restrict__ mask, const float* __restrict__ trans)
{
    int t = threadIdx.x;
    int g = blockIdx.x*256 + t;
    float v = 0.f;
    if (mask[g]){
        int l = labels[g];
        v = emit[(size_t)g*Ln + l];
        if (g & 511) v += trans[labels[g-1]*Ln + l];
    }
    #pragma unroll
    for (int o = 16; o; o >>= 1) v += __shfl_down_sync(0xffffffffu, v, o);
    __shared__ float sp[8];
    if ((t & 31) == 0) sp[t >> 5] = v;
    __syncthreads();
    if (t == 0){
        double tot = 0.0;
        #pragma unroll
        for (int i = 0; i < 8; ++i) tot += (double)sp[i];
        atomicAdd(&g_score, tot);
    }
}

// ---------------------------------------------------------------------------
// K3: alpha.  Per block: 128 pairs.  est column-major [j][p] (pitch 132).
// Inner loop per j: 1 T-LDS.128 + 2 e-LDS.128 (broadcast) + 32 FFMA.
// ---------------------------------------------------------------------------
__global__ __launch_bounds__(256, 4) void alpha_kernel(
    const float* __restrict__ emit, const int* __restrict__ mask)
{
    __shared__ float sT[Ln*Ln];        // [j*64 + i]
    __shared__ float est[Ln*EPITCH];   // [j*132 + p]
    __shared__ float flags[PPB];

    int t  = threadIdx.x;
    int p0 = blockIdx.x * PPB;

    // expT tile (coalesced, conflict-free)
    {
        const float4* gT4 = (const float4*)gExpT;
        float4* sT4 = (float4*)sT;
        #pragma unroll
        for (int it = 0; it < 4; ++it) sT4[t + it*256] = gT4[t + it*256];
    }
    // emit tile: coalesced float4 read into regs, ex2, transposed scalar STS.
    {
        int p  = t >> 1;                       // 0..127
        int jh = (t & 1) * 32;                 // half-row
        const float4* src = (const float4*)(emit + ((size_t)(p0 + Sn + p))*Ln + jh);
        #pragma unroll
        for (int q = 0; q < 8; ++q){
            float4 v = src[q];
            int j = jh + 4*q;
            est[(j  )*EPITCH + p] = ex2f(v.x * LOG2E);
            est[(j+1)*EPITCH + p] = ex2f(v.y * LOG2E);
            est[(j+2)*EPITCH + p] = ex2f(v.z * LOG2E);
            est[(j+3)*EPITCH + p] = ex2f(v.w * LOG2E);
        }
    }
    if (t < PPB){
        int p = p0 + t;
        int b = 1 + (p >> 9), s = p & 511;
        flags[t] = mask[b*Sn + s] ? 1.0f : 0.0f;
    }
    __syncthreads();

    const int i4 = t & 15;             // i = 4*i4 .. 4*i4+3
    const int pg = t >> 4;             // p = pg*8 .. pg*8+7
    float acc[4][8];
    #pragma unroll
    for (int k = 0; k < 4; ++k)
        #pragma unroll
        for (int pp = 0; pp < 8; ++pp) acc[k][pp] = 0.0f;

    const float4* pT = (const float4*)(sT) + i4;         // step 16 per j
    const float4* pE = (const float4*)(est) + pg*2;      // step 33 per j

    #pragma unroll 8
    for (int j = 0; j < 64; ++j){
        float4 tv = pT[j*16];
        float4 ea = pE[j*33];
        float4 eb = pE[j*33 + 1];
        float e[8] = {ea.x, ea.y, ea.z, ea.w, eb.x, eb.y, eb.z, eb.w};
        #pragma unroll
        for (int pp = 0; pp < 8; ++pp){
            acc[0][pp] = fmaf(tv.x, e[pp], acc[0][pp]);
            acc[1][pp] = fmaf(tv.y, e[pp], acc[1][pp]);
            acc[2][pp] = fmaf(tv.z, e[pp], acc[2][pp]);
            acc[3][pp] = fmaf(tv.w, e[pp], acc[3][pp]);
        }
    }

    // log2 + masked accumulate
    float csum[4] = {0.f, 0.f, 0.f, 0.f};
    #pragma unroll
    for (int pp = 0; pp < 8; ++pp){
        float f = flags[(pg << 3) + pp];
        #pragma unroll
        for (int k = 0; k < 4; ++k) csum[k] += f * lg2f_(acc[k][pp]);
    }

    __syncthreads();
    float* red = est;                  // reuse: red[pg*64 + i]
    #pragma unroll
    for (int k = 0; k < 4; ++k) red[pg*64 + (i4 << 2) + k] = csum[k];
    __syncthreads();

    if (t < Ln){
        float s = 0.f;
        #pragma unroll
        for (int g = 0; g < 16; ++g) s += red[g*64 + t];
        atomicAdd(&g_alpha[t], s * LN2f);
    }
}

// ---------------------------------------------------------------------------
// K4: finalize (parallel, float LSE — no serial double exp).
// ---------------------------------------------------------------------------
__global__ void fin_kernel(const float* __restrict__ emit, float* __restrict__ out){
    int t = threadIdx.x;                       // 64 threads
    float a = g_alpha[t] + emit[t];            // + emit[0,0,:]
    // max over 64
    float m = a;
    #pragma unroll
    for (int o = 16; o; o >>= 1) m = fmaxf(m, __shfl_xor_sync(0xffffffffu, m, o));
    __shared__ float sm[2];
    if ((t & 31) == 0) sm[t >> 5] = m;
    __syncthreads();
    m = fmaxf(sm[0], sm[1]);
    float e = ex2f((a - m) * LOG2E);
    #pragma unroll
    for (int o = 16; o; o >>= 1) e += __shfl_xor_sync(0xffffffffu, e, o);
    __shared__ float se[2];
    if ((t & 31) == 0) se[t >> 5] = e;
    __syncthreads();
    if (t == 0){
        double logZ = (double)m + (double)(LN2f * lg2f_(se[0] + se[1]));
        out[0] = (float)((logZ - g_score) / (double)Bn);
    }
}

// ---------------------------------------------------------------------------
extern "C" void kernel_launch(void* const* d_in, const int* in_sizes, int n_in,
                              void* d_out, int out_size)
{
    const float* emit   = (const float*)d_in[0];
    const int*   labels = (const int*)d_in[1];
    const int*   mask   = (const int*)d_in[2];
    const float* trans  = (const float*)d_in[3];
    const float* strans = (const float*)d_in[4];
    const float* etrans = (const float*)d_in[5];
    float* out = (float*)d_out;

    initz_kernel<<<16, 256>>>(trans);
    score_ends_kernel<<<Bn, 128>>>(labels, mask, strans, etrans);
    score_main_kernel<<<NQ/256, 256>>>(emit, labels, mask, trans);
    alpha_kernel<<<NBLK, 256>>>(emit, mask);     // launch index 3 (ncu slot)
    fin_kernel<<<1, 64>>>(emit, out);
}